// round 16
// baseline (speedup 1.0000x reference)
#include <cuda_runtime.h>
#include <math.h>

#define TOTAL_V 991
#define BATCH   2048
#define NPARTS  20
#define NEPS    9

__device__ __forceinline__ float ex2f_(float x){ float r; asm("ex2.approx.ftz.f32 %0, %1;" : "=f"(r) : "f"(x)); return r; }
__device__ __forceinline__ float lg2f_(float x){ float r; asm("lg2.approx.ftz.f32 %0, %1;" : "=f"(r) : "f"(x)); return r; }

// {n, ld (stride, ld/4 odd), soff, 0}; launches grouped by EXACT nc4=ceil(n/4):
__constant__ int4 c_desc[NPARTS] = {
    {40,44,611,0},
    {34,36,286,0},{35,36,752,0},
    {50,52,879,0},
    {41,44,320,0},{41,44,711,0},{42,44,569,0},{43,44,106,0},{44,44,423,0},{44,44,467,0},
    {45,52,  0,0},{45,52,149,0},
    {28,28,851,0},
    {61,68, 45,0},{62,68,361,0},{62,68,929,0},{64,68,787,0},
    {58,60,511,0},{60,60,651,0},
    {92,92,194,0}
};

// region 0: xy/quad sums, region 1: self sums (quad parts leave region1 = 0 forever)
__device__ float g_scratch[2 * NPARTS * BATCH];
#define NRED 40
__device__ float g_partial[NRED];

#define LOG2E_ 1.44269504088896340736f
#define LN2_   0.69314718055994530942f

// eps levels: 64,16,4,1,.25,.0625,.015625,.00390625,.0025
// skip-max (nomax) for e<3; fold: e0 -> 0, e1/e2 -> 16 (bounds-proven safe)
#define EPS_OF(e) ((e)==0?64.f:(e)==1?16.f:(e)==2?4.f:(e)==3?1.f:(e)==4?0.25f:(e)==5?0.0625f:(e)==6?0.015625f:(e)==7?0.00390625f:0.0025f)
#define MFOLD_OF(e) ((e)==0?0.f:16.f)

// Fully-unrolled fused two-pass logsumexp over exactly NC4 float4s (no guards).
// Pads: C=+1e30, vec=-1e30 -> z_pad huge-negative finite; fmax loses, ex2 FTZ->0.
template<int NC4>
__device__ __forceinline__ float lse_row(const float4* __restrict__ r4,
                                         const float4* __restrict__ v4,
                                         float nk, float c1, float c2)
{
    float4 z[NC4];
    float M0 = -3.0e38f, M1 = -3.0e38f;
    #pragma unroll
    for (int c = 0; c < NC4; c++) {
        float4 a = r4[c]; float4 w = v4[c];
        z[c].x = fmaf(a.x, nk, w.x);
        z[c].y = fmaf(a.y, nk, w.y);
        z[c].z = fmaf(a.z, nk, w.z);
        z[c].w = fmaf(a.w, nk, w.w);
        M0 = fmaxf(M0, fmaxf(z[c].x, z[c].y));
        M1 = fmaxf(M1, fmaxf(z[c].z, z[c].w));
    }
    const float M = fmaxf(M0, M1);
    float S0 = 0.f, S1 = 0.f, S2 = 0.f, S3 = 0.f;
    #pragma unroll
    for (int c = 0; c < NC4; c++) {
        S0 += ex2f_(z[c].x - M);
        S1 += ex2f_(z[c].y - M);
        S2 += ex2f_(z[c].z - M);
        S3 += ex2f_(z[c].w - M);
    }
    return fmaf(c1, M + lg2f_((S0 + S1) + (S2 + S3)), c2);
}

// No-max variant: fixed stabilizer fold pre-applied to the shared vector.
template<int NC4>
__device__ __forceinline__ float lse_row_nomax(const float4* __restrict__ r4,
                                               const float4* __restrict__ v4,
                                               float nk, float c1, float c2m)
{
    float S0 = 0.f, S1 = 0.f, S2 = 0.f, S3 = 0.f;
    #pragma unroll
    for (int c = 0; c < NC4; c++) {
        float4 a = r4[c]; float4 w = v4[c];
        S0 += ex2f_(fmaf(a.x, nk, w.x));
        S1 += ex2f_(fmaf(a.y, nk, w.y));
        S2 += ex2f_(fmaf(a.z, nk, w.z));
        S3 += ex2f_(fmaf(a.w, nk, w.w));
    }
    return fmaf(c1, lg2f_((S0 + S1) + (S2 + S3)), c2m);
}

// The shared eps mainloop body, fully unrolled so all per-level constants are literals.
template<int NC4, int NBUF>
__device__ __forceinline__ float eps_mainloop(float* __restrict__ V, int ld, int g, int rg, int r,
                                              bool act, const float4* __restrict__ rr, float l2n)
{
    float myv = 0.f;
    #pragma unroll
    for (int e = 0; e < NEPS; e++) {
        const float eps = EPS_OF(e);
        const float k   = LOG2E_ / eps;
        const float nk  = -k;
        const float c1  = -eps * LN2_;
        const float c2  = eps * LN2_ * l2n;   // -eps * log(1/n)

        if (e < 3) {
            const float Mf = MFOLD_OF(e);
            if (act) (V + ((e & 1) * NBUF + g) * ld)[r] = fmaf(myv, k, -Mf);
            __syncthreads();
            if (act) {
                const float4* vv = (const float4*)(V + ((e & 1) * NBUF + rg) * ld);
                const float c2m = fmaf(c1, Mf, c2);
                myv = 0.5f * (myv + lse_row_nomax<NC4>(rr, vv, nk, c1, c2m));
            }
        } else {
            if (act) (V + ((e & 1) * NBUF + g) * ld)[r] = myv * k;
            __syncthreads();
            if (act) {
                const float4* vv = (const float4*)(V + ((e & 1) * NBUF + rg) * ld);
                myv = 0.5f * (myv + lse_row<NC4>(rr, vv, nk, c1, c2));
            }
        }
    }
    return myv;
}

template<int NC4>
__device__ __forceinline__ void build_row(float* __restrict__ rowp,
                                          float lx, float ly, float lz, float hl2,
                                          const float* __restrict__ vx, const float* __restrict__ vy,
                                          const float* __restrict__ vz, const float* __restrict__ v2,
                                          int n)
{
    const float4* ax4 = (const float4*)vx;
    const float4* ay4 = (const float4*)vy;
    const float4* az4 = (const float4*)vz;
    const float4* a24 = (const float4*)v2;
    float4* row4 = (float4*)rowp;
    #pragma unroll
    for (int c = 0; c < NC4; c++) {
        float4 ax = ax4[c], ay = ay4[c], az = az4[c], a2 = a24[c];
        float4 o;
        o.x = fmaf(-lx, ax.x, fmaf(-ly, ay.x, fmaf(-lz, az.x, fmaf(0.5f, a2.x, hl2))));
        o.y = fmaf(-lx, ax.y, fmaf(-ly, ay.y, fmaf(-lz, az.y, fmaf(0.5f, a2.y, hl2))));
        o.z = fmaf(-lx, ax.z, fmaf(-ly, ay.z, fmaf(-lz, az.z, fmaf(0.5f, a2.z, hl2))));
        o.w = fmaf(-lx, ax.w, fmaf(-ly, ay.w, fmaf(-lz, az.w, fmaf(0.5f, a2.w, hl2))));
        row4[c] = o;
    }
    for (int j = n; j < 4 * NC4; j++) rowp[j] = 1e30f;   // overwrite tail garbage
}

// Pair kernel: 2n dense rows; self-bit from blockIdx selects xy (Cxy/Cyx) or self (Cxx/Cyy).
// smem = (2n + 12) * ld floats. One barrier per eps (double-buffered scaled vectors).
template<int NC4, int THREADS, int MINCTAS>
__global__ void __launch_bounds__(THREADS, MINCTAS)
pair_kernel(const float* __restrict__ pred, const float* __restrict__ pc, int first)
{
    const unsigned u = blockIdx.x;
    const int pl   = u >> 12;
    const int self = (u >> 11) & 1;
    const int b    = u & 2047;
    const int4 d = c_desc[first + pl];
    const int n = d.x, ld = d.y, soff = d.z;

    extern __shared__ float sm[];
    const int msz = n * ld;
    float* V  = sm + 2 * msz;          // scaled: (buf*2 + g)*ld ; geometry at +4*ld
    float* xx = V + 4*ld;  float* xy = V + 5*ld;  float* xz = V + 6*ld;  float* x2 = V + 7*ld;
    float* yx = V + 8*ld;  float* yy = V + 9*ld;  float* yz = V + 10*ld; float* y2 = V + 11*ld;

    const int t = threadIdx.x;
    const int g = (t >= n) ? 1 : 0;
    const int r = t - g * n;
    const bool act = (t < 2 * n);

    if (act && g == 0) {
        const float* X = pred + ((size_t)b * TOTAL_V + soff + r) * 3;
        float ax = X[0], ay = X[1], az = X[2];
        xx[r] = ax; xy[r] = ay; xz[r] = az;
        x2[r] = ax*ax + ay*ay + az*az;
    }
    if (act && g == 1) {
        const float* Y = pc + ((size_t)b * TOTAL_V + soff + r) * 3;
        float bx = Y[0], by = Y[1], bz = Y[2];
        yx[r] = bx; yy[r] = by; yz[r] = bz;
        y2[r] = bx*bx + by*by + bz*bz;
    }
    for (int j = n + t; j < ld; j += THREADS) {
        #pragma unroll
        for (int a = 0; a < 4; a++) V[a*ld + j] = -1e30f;
    }
    __syncthreads();

    if (act) {
        // xy: g0 row of Cxy(X_r vs Y), g1 row of Cyx(Y_r vs X). self: g0 Cxx, g1 Cyy.
        const bool lX = (g == 0);
        const bool rX = self ? (g == 0) : (g == 1);
        const float lx = lX ? xx[r] : yx[r];
        const float ly = lX ? xy[r] : yy[r];
        const float lz = lX ? xz[r] : yz[r];
        const float hl2 = 0.5f * (lX ? x2[r] : y2[r]);
        build_row<NC4>(sm + g*msz + r*ld, lx, ly, lz, hl2,
                       rX ? xx : yx, rX ? xy : yy, rX ? xz : yz, rX ? x2 : y2, n);
    }

    const float l2n = lg2f_((float)n);
    const int rg = self ? g : (1 - g);
    const float4* rr = (const float4*)(sm + g*msz + (size_t)r*ld);

    const float myv = eps_mainloop<NC4, 2>(V, ld, g, rg, r, act, rr, l2n);
    __syncthreads();

    float val = act ? (self ? -myv : myv) : 0.f;
    #pragma unroll
    for (int o = 16; o; o >>= 1) val += __shfl_xor_sync(0xffffffffu, val, o);
    if ((t & 31) == 0) V[t >> 5] = val;
    __syncthreads();
    if (t == 0) {
        float s = 0.f;
        #pragma unroll
        for (int w = 0; w < THREADS / 32; w++) s += V[w];
        g_scratch[(self ? NPARTS : 0) * BATCH + ((first + pl) * BATCH + b)] = s / (float)n;
    }
}

// Quad kernel: 4n dense rows, all four sweeps in one CTA. smem=(4n+16)*ld.
template<int NC4, int THREADS, int MINCTAS>
__global__ void __launch_bounds__(THREADS, MINCTAS)
quad_kernel(const float* __restrict__ pred, const float* __restrict__ pc, int first)
{
    const int pl = blockIdx.x >> 11;
    const int b  = blockIdx.x & 2047;
    const int4 d = c_desc[first + pl];
    const int n = d.x, ld = d.y, soff = d.z;

    extern __shared__ float sm[];
    const int msz = n * ld;
    float* V  = sm + 4 * msz;          // scaled: (buf*4 + g)*ld ; geometry at +8*ld
    float* xx = V + 8*ld;  float* xy = V + 9*ld;  float* xz = V + 10*ld; float* x2 = V + 11*ld;
    float* yx = V + 12*ld; float* yy = V + 13*ld; float* yz = V + 14*ld; float* y2 = V + 15*ld;

    const int t = threadIdx.x;
    const int g = t / n;               // one runtime divide
    const int r = t - g * n;
    const bool act = (g < 4);

    if (act && g == 0) {
        const float* X = pred + ((size_t)b * TOTAL_V + soff + r) * 3;
        float ax = X[0], ay = X[1], az = X[2];
        xx[r] = ax; xy[r] = ay; xz[r] = az;
        x2[r] = ax*ax + ay*ay + az*az;
    }
    if (act && g == 1) {
        const float* Y = pc + ((size_t)b * TOTAL_V + soff + r) * 3;
        float bx = Y[0], by = Y[1], bz = Y[2];
        yx[r] = bx; yy[r] = by; yz[r] = bz;
        y2[r] = bx*bx + by*by + bz*bz;
    }
    for (int j = n + t; j < ld; j += THREADS) {
        #pragma unroll
        for (int a = 0; a < 8; a++) V[a*ld + j] = -1e30f;
    }
    __syncthreads();

    if (act) {
        // g0: Cxy(X,Y) g1: Cyx(Y,X) g2: Cxx g3: Cyy
        const bool lX = (g == 0) || (g == 2);
        const bool rX = (g == 1) || (g == 2);
        const float lx = lX ? xx[r] : yx[r];
        const float ly = lX ? xy[r] : yy[r];
        const float lz = lX ? xz[r] : yz[r];
        const float hl2 = 0.5f * (lX ? x2[r] : y2[r]);
        build_row<NC4>(sm + g*msz + r*ld, lx, ly, lz, hl2,
                       rX ? xx : yx, rX ? xy : yy, rX ? xz : yz, rX ? x2 : y2, n);
    }

    const float l2n = lg2f_((float)n);
    const int rg = (g < 2) ? (1 - g) : g;
    const float4* rr = (const float4*)(sm + g*msz + (size_t)r*ld);

    const float myv = eps_mainloop<NC4, 4>(V, ld, g, rg, r, act, rr, l2n);
    __syncthreads();

    float val = act ? ((g < 2) ? myv : -myv) : 0.f;
    #pragma unroll
    for (int o = 16; o; o >>= 1) val += __shfl_xor_sync(0xffffffffu, val, o);
    if ((t & 31) == 0) V[t >> 5] = val;
    __syncthreads();
    if (t == 0) {
        float s = 0.f;
        #pragma unroll
        for (int w = 0; w < THREADS / 32; w++) s += V[w];
        g_scratch[(first + pl) * BATCH + b] = s / (float)n;
    }
}

// Two-stage deterministic reduction.
__global__ void reduce_partial_kernel()
{
    __shared__ float red[32];
    const int chunk = (2 * NPARTS * BATCH) / NRED;   // 2048
    const int base = blockIdx.x * chunk;
    float s = 0.f;
    for (int i = threadIdx.x; i < chunk; i += 1024) s += g_scratch[base + i];
    #pragma unroll
    for (int o = 16; o; o >>= 1) s += __shfl_xor_sync(0xffffffffu, s, o);
    if ((threadIdx.x & 31) == 0) red[threadIdx.x >> 5] = s;
    __syncthreads();
    if (threadIdx.x < 32) {
        float v = red[threadIdx.x];
        #pragma unroll
        for (int o = 16; o; o >>= 1) v += __shfl_xor_sync(0xffffffffu, v, o);
        if (threadIdx.x == 0) g_partial[blockIdx.x] = v;
    }
}

__global__ void reduce_final_kernel(float* __restrict__ out)
{
    if (threadIdx.x == 0) {
        float acc = 0.f;
        for (int i = 0; i < NRED; i++) acc += g_partial[i];
        out[0] = acc * (1.0f / (float)BATCH);
    }
}

extern "C" void kernel_launch(void* const* d_in, const int* in_sizes, int n_in,
                              void* d_out, int out_size)
{
    const float* pred = (const float*)d_in[0];
    const float* pc   = (const float*)d_in[1];

    const int smQ10 = (4*40 + 16) * 44 * 4;   // 30,976
    const int smQ9  = (4*35 + 16) * 36 * 4;   // 22,464
    const int smQ13 = (4*50 + 16) * 52 * 4;   // 44,928
    const int smP11 = (2*44 + 12) * 44 * 4;   // 17,600
    const int smP12 = (2*45 + 12) * 52 * 4;   // 21,216
    const int smP7  = (2*28 + 12) * 28 * 4;   //  7,616
    const int smP16 = (2*64 + 12) * 68 * 4;   // 38,080
    const int smP15 = (2*60 + 12) * 60 * 4;   // 31,680
    const int smP23 = (2*92 + 12) * 92 * 4;   // 72,128

    cudaFuncSetAttribute((const void*)quad_kernel<10,160,5>, cudaFuncAttributeMaxDynamicSharedMemorySize, smQ10);
    cudaFuncSetAttribute((const void*)quad_kernel< 9,160,6>, cudaFuncAttributeMaxDynamicSharedMemorySize, smQ9);
    cudaFuncSetAttribute((const void*)quad_kernel<13,224,4>, cudaFuncAttributeMaxDynamicSharedMemorySize, smQ13);
    cudaFuncSetAttribute((const void*)pair_kernel<11, 96,10>, cudaFuncAttributeMaxDynamicSharedMemorySize, smP11);
    cudaFuncSetAttribute((const void*)pair_kernel<12, 96,10>, cudaFuncAttributeMaxDynamicSharedMemorySize, smP12);
    cudaFuncSetAttribute((const void*)pair_kernel< 7, 64,15>, cudaFuncAttributeMaxDynamicSharedMemorySize, smP7);
    cudaFuncSetAttribute((const void*)pair_kernel<16,128, 5>, cudaFuncAttributeMaxDynamicSharedMemorySize, smP16);
    cudaFuncSetAttribute((const void*)pair_kernel<15,128, 5>, cudaFuncAttributeMaxDynamicSharedMemorySize, smP15);
    cudaFuncSetAttribute((const void*)pair_kernel<23,192, 2>, cudaFuncAttributeMaxDynamicSharedMemorySize, smP23);

    // Multi-stream fork/join (capture-safe); created once on the uncaptured correctness call.
    static cudaStream_t sx[3];
    static cudaEvent_t evr, evd[3];
    static int sok = -1;
    if (sok < 0) {
        sok = 1;
        for (int i = 0; i < 3; i++)
            if (cudaStreamCreateWithFlags(&sx[i], cudaStreamNonBlocking) != cudaSuccess) sok = 0;
        if (cudaEventCreateWithFlags(&evr, cudaEventDisableTiming) != cudaSuccess) sok = 0;
        for (int i = 0; i < 3; i++)
            if (cudaEventCreateWithFlags(&evd[i], cudaEventDisableTiming) != cudaSuccess) sok = 0;
    }
    cudaStream_t s1 = 0, s2 = 0, s3 = 0;
    if (sok) {
        cudaEventRecord(evr, 0);
        for (int i = 0; i < 3; i++) cudaStreamWaitEvent(sx[i], evr, 0);
        s1 = sx[0]; s2 = sx[1]; s3 = sx[2];
    }

    // Rebalanced packing (work units = 4*n*NC4 per part):
    // S0: p23 8464 + p12 4320 + p7 784           = 13,568
    // S1: p11 11220 + q9 2484                    = 13,704
    // S2: p16[13,14] 7872 + p15[17] 3480 + q13   = 13,952
    // S3: p16[15,16] 8064 + p15[18] 3600 + q10   = 13,264
    pair_kernel<23,192, 2><<<1 * 2 * BATCH, 192, smP23, 0>>>(pred, pc, 19);  // n=92
    pair_kernel<12, 96,10><<<2 * 2 * BATCH,  96, smP12, 0>>>(pred, pc, 10);  // n=45,45
    pair_kernel< 7, 64,15><<<1 * 2 * BATCH,  64, smP7 , 0>>>(pred, pc, 12);  // n=28

    pair_kernel<11, 96,10><<<6 * 2 * BATCH,  96, smP11, s1>>>(pred, pc,  4); // n=41..44
    quad_kernel< 9,160,6> <<<2 * BATCH,     160, smQ9 , s1>>>(pred, pc,  1); // n=34,35

    pair_kernel<16,128, 5><<<2 * 2 * BATCH, 128, smP16, s2>>>(pred, pc, 13); // n=61,62
    pair_kernel<15,128, 5><<<1 * 2 * BATCH, 128, smP15, s2>>>(pred, pc, 17); // n=58
    quad_kernel<13,224,4> <<<1 * BATCH,     224, smQ13, s2>>>(pred, pc,  3); // n=50

    pair_kernel<16,128, 5><<<2 * 2 * BATCH, 128, smP16, s3>>>(pred, pc, 15); // n=62,64
    pair_kernel<15,128, 5><<<1 * 2 * BATCH, 128, smP15, s3>>>(pred, pc, 18); // n=60
    quad_kernel<10,160,5> <<<1 * BATCH,     160, smQ10, s3>>>(pred, pc,  0); // n=40

    if (sok) {
        for (int i = 0; i < 3; i++) {
            cudaEventRecord(evd[i], sx[i]);
            cudaStreamWaitEvent(0, evd[i], 0);
        }
    }
    reduce_partial_kernel<<<NRED, 1024, 0, 0>>>();
    reduce_final_kernel<<<1, 64, 0, 0>>>((float*)d_out);
}

// round 17
// speedup vs baseline: 1.0270x; 1.0270x over previous
#include <cuda_runtime.h>
#include <math.h>

#define TOTAL_V 991
#define BATCH   2048
#define NPARTS  20
#define NEPS    9

__device__ __forceinline__ float ex2f_(float x){ float r; asm("ex2.approx.ftz.f32 %0, %1;" : "=f"(r) : "f"(x)); return r; }
__device__ __forceinline__ float lg2f_(float x){ float r; asm("lg2.approx.ftz.f32 %0, %1;" : "=f"(r) : "f"(x)); return r; }

// {n, ld (stride, ld/4 odd), soff, 0}; launches grouped by EXACT nc4=ceil(n/4):
__constant__ int4 c_desc[NPARTS] = {
    {40,44,611,0},
    {34,36,286,0},{35,36,752,0},
    {50,52,879,0},
    {41,44,320,0},{41,44,711,0},{42,44,569,0},{43,44,106,0},{44,44,423,0},{44,44,467,0},
    {45,52,  0,0},{45,52,149,0},
    {28,28,851,0},
    {61,68, 45,0},{62,68,361,0},{62,68,929,0},{64,68,787,0},
    {58,60,511,0},{60,60,651,0},
    {92,92,194,0}
};

// region 0: xy/quad sums, region 1: self sums (quad parts leave region1 = 0 forever)
__device__ float g_scratch[2 * NPARTS * BATCH];
#define NRED 40
__device__ float g_partial[NRED];

#define LOG2E_ 1.44269504088896340736f
#define LN2_   0.69314718055994530942f

// eps levels: 64,16,4,1,.25,.0625,.015625,.00390625,.0025
// skip-max (nomax) for e<3; fold: e0 -> 0, e1/e2 -> 16 (bounds-proven safe)
#define EPS_OF(e) ((e)==0?64.f:(e)==1?16.f:(e)==2?4.f:(e)==3?1.f:(e)==4?0.25f:(e)==5?0.0625f:(e)==6?0.015625f:(e)==7?0.00390625f:0.0025f)
#define MFOLD_OF(e) ((e)==0?0.f:16.f)

// Fully-unrolled fused two-pass logsumexp over exactly NC4 float4s (no guards).
// Pads: C=+1e30, vec=-1e30 -> z_pad huge-negative finite; fmax loses, ex2 FTZ->0.
template<int NC4>
__device__ __forceinline__ float lse_row(const float4* __restrict__ r4,
                                         const float4* __restrict__ v4,
                                         float nk, float c1, float c2)
{
    float4 z[NC4];
    float M0 = -3.0e38f, M1 = -3.0e38f;
    #pragma unroll
    for (int c = 0; c < NC4; c++) {
        float4 a = r4[c]; float4 w = v4[c];
        z[c].x = fmaf(a.x, nk, w.x);
        z[c].y = fmaf(a.y, nk, w.y);
        z[c].z = fmaf(a.z, nk, w.z);
        z[c].w = fmaf(a.w, nk, w.w);
        M0 = fmaxf(M0, fmaxf(z[c].x, z[c].y));
        M1 = fmaxf(M1, fmaxf(z[c].z, z[c].w));
    }
    const float M = fmaxf(M0, M1);
    float S0 = 0.f, S1 = 0.f, S2 = 0.f, S3 = 0.f;
    #pragma unroll
    for (int c = 0; c < NC4; c++) {
        S0 += ex2f_(z[c].x - M);
        S1 += ex2f_(z[c].y - M);
        S2 += ex2f_(z[c].z - M);
        S3 += ex2f_(z[c].w - M);
    }
    return fmaf(c1, M + lg2f_((S0 + S1) + (S2 + S3)), c2);
}

// No-max variant: fixed stabilizer fold pre-applied to the shared vector.
template<int NC4>
__device__ __forceinline__ float lse_row_nomax(const float4* __restrict__ r4,
                                               const float4* __restrict__ v4,
                                               float nk, float c1, float c2m)
{
    float S0 = 0.f, S1 = 0.f, S2 = 0.f, S3 = 0.f;
    #pragma unroll
    for (int c = 0; c < NC4; c++) {
        float4 a = r4[c]; float4 w = v4[c];
        S0 += ex2f_(fmaf(a.x, nk, w.x));
        S1 += ex2f_(fmaf(a.y, nk, w.y));
        S2 += ex2f_(fmaf(a.z, nk, w.z));
        S3 += ex2f_(fmaf(a.w, nk, w.w));
    }
    return fmaf(c1, lg2f_((S0 + S1) + (S2 + S3)), c2m);
}

// Level-0 variant: vector is identically zero (myv=0, fold=0) -> no shared vector at all.
template<int NC4>
__device__ __forceinline__ float lse_row_novec(const float4* __restrict__ r4,
                                               float nk, float c1, float c2)
{
    float S0 = 0.f, S1 = 0.f, S2 = 0.f, S3 = 0.f;
    #pragma unroll
    for (int c = 0; c < NC4; c++) {
        float4 a = r4[c];
        S0 += ex2f_(a.x * nk);
        S1 += ex2f_(a.y * nk);
        S2 += ex2f_(a.z * nk);
        S3 += ex2f_(a.w * nk);
    }
    return fmaf(c1, lg2f_((S0 + S1) + (S2 + S3)), c2);
}

// The shared eps mainloop body, fully unrolled so all per-level constants are literals.
// Level 0: no vector store, no vector load, NO BARRIER (each thread reads only its own row,
// which it wrote itself; geometry was barriered before the build).
template<int NC4, int NBUF>
__device__ __forceinline__ float eps_mainloop(float* __restrict__ V, int ld, int g, int rg, int r,
                                              bool act, const float4* __restrict__ rr, float l2n)
{
    float myv = 0.f;
    #pragma unroll
    for (int e = 0; e < NEPS; e++) {
        const float eps = EPS_OF(e);
        const float k   = LOG2E_ / eps;
        const float nk  = -k;
        const float c1  = -eps * LN2_;
        const float c2  = eps * LN2_ * l2n;   // -eps * log(1/n)

        if (e == 0) {
            if (act) myv = 0.5f * lse_row_novec<NC4>(rr, nk, c1, c2);
        } else if (e < 3) {
            const float Mf = MFOLD_OF(e);
            if (act) (V + ((e & 1) * NBUF + g) * ld)[r] = fmaf(myv, k, -Mf);
            __syncthreads();
            if (act) {
                const float4* vv = (const float4*)(V + ((e & 1) * NBUF + rg) * ld);
                const float c2m = fmaf(c1, Mf, c2);
                myv = 0.5f * (myv + lse_row_nomax<NC4>(rr, vv, nk, c1, c2m));
            }
        } else {
            if (act) (V + ((e & 1) * NBUF + g) * ld)[r] = myv * k;
            __syncthreads();
            if (act) {
                const float4* vv = (const float4*)(V + ((e & 1) * NBUF + rg) * ld);
                myv = 0.5f * (myv + lse_row<NC4>(rr, vv, nk, c1, c2));
            }
        }
    }
    return myv;
}

template<int NC4>
__device__ __forceinline__ void build_row(float* __restrict__ rowp,
                                          float lx, float ly, float lz, float hl2,
                                          const float* __restrict__ vx, const float* __restrict__ vy,
                                          const float* __restrict__ vz, const float* __restrict__ v2,
                                          int n)
{
    const float4* ax4 = (const float4*)vx;
    const float4* ay4 = (const float4*)vy;
    const float4* az4 = (const float4*)vz;
    const float4* a24 = (const float4*)v2;
    float4* row4 = (float4*)rowp;
    #pragma unroll
    for (int c = 0; c < NC4; c++) {
        float4 ax = ax4[c], ay = ay4[c], az = az4[c], a2 = a24[c];
        float4 o;
        o.x = fmaf(-lx, ax.x, fmaf(-ly, ay.x, fmaf(-lz, az.x, fmaf(0.5f, a2.x, hl2))));
        o.y = fmaf(-lx, ax.y, fmaf(-ly, ay.y, fmaf(-lz, az.y, fmaf(0.5f, a2.y, hl2))));
        o.z = fmaf(-lx, ax.z, fmaf(-ly, ay.z, fmaf(-lz, az.z, fmaf(0.5f, a2.z, hl2))));
        o.w = fmaf(-lx, ax.w, fmaf(-ly, ay.w, fmaf(-lz, az.w, fmaf(0.5f, a2.w, hl2))));
        row4[c] = o;
    }
    for (int j = n; j < 4 * NC4; j++) rowp[j] = 1e30f;   // overwrite tail garbage
}

// Pair kernel: 2n dense rows; self-bit from blockIdx selects xy (Cxy/Cyx) or self (Cxx/Cyy).
// smem = (2n + 12) * ld floats. One barrier per eps (double-buffered scaled vectors).
template<int NC4, int THREADS, int MINCTAS>
__global__ void __launch_bounds__(THREADS, MINCTAS)
pair_kernel(const float* __restrict__ pred, const float* __restrict__ pc, int first)
{
    const unsigned u = blockIdx.x;
    const int pl   = u >> 12;
    const int self = (u >> 11) & 1;
    const int b    = u & 2047;
    const int4 d = c_desc[first + pl];
    const int n = d.x, ld = d.y, soff = d.z;

    extern __shared__ float sm[];
    const int msz = n * ld;
    float* V  = sm + 2 * msz;          // scaled: (buf*2 + g)*ld ; geometry at +4*ld
    float* xx = V + 4*ld;  float* xy = V + 5*ld;  float* xz = V + 6*ld;  float* x2 = V + 7*ld;
    float* yx = V + 8*ld;  float* yy = V + 9*ld;  float* yz = V + 10*ld; float* y2 = V + 11*ld;

    const int t = threadIdx.x;
    const int g = (t >= n) ? 1 : 0;
    const int r = t - g * n;
    const bool act = (t < 2 * n);

    if (act && g == 0) {
        const float* X = pred + ((size_t)b * TOTAL_V + soff + r) * 3;
        float ax = X[0], ay = X[1], az = X[2];
        xx[r] = ax; xy[r] = ay; xz[r] = az;
        x2[r] = ax*ax + ay*ay + az*az;
    }
    if (act && g == 1) {
        const float* Y = pc + ((size_t)b * TOTAL_V + soff + r) * 3;
        float bx = Y[0], by = Y[1], bz = Y[2];
        yx[r] = bx; yy[r] = by; yz[r] = bz;
        y2[r] = bx*bx + by*by + bz*bz;
    }
    for (int j = n + t; j < ld; j += THREADS) {
        #pragma unroll
        for (int a = 0; a < 4; a++) V[a*ld + j] = -1e30f;
    }
    __syncthreads();

    if (act) {
        // xy: g0 row of Cxy(X_r vs Y), g1 row of Cyx(Y_r vs X). self: g0 Cxx, g1 Cyy.
        const bool lX = (g == 0);
        const bool rX = self ? (g == 0) : (g == 1);
        const float lx = lX ? xx[r] : yx[r];
        const float ly = lX ? xy[r] : yy[r];
        const float lz = lX ? xz[r] : yz[r];
        const float hl2 = 0.5f * (lX ? x2[r] : y2[r]);
        build_row<NC4>(sm + g*msz + r*ld, lx, ly, lz, hl2,
                       rX ? xx : yx, rX ? xy : yy, rX ? xz : yz, rX ? x2 : y2, n);
    }

    const float l2n = lg2f_((float)n);
    const int rg = self ? g : (1 - g);
    const float4* rr = (const float4*)(sm + g*msz + (size_t)r*ld);

    const float myv = eps_mainloop<NC4, 2>(V, ld, g, rg, r, act, rr, l2n);
    __syncthreads();

    float val = act ? (self ? -myv : myv) : 0.f;
    #pragma unroll
    for (int o = 16; o; o >>= 1) val += __shfl_xor_sync(0xffffffffu, val, o);
    if ((t & 31) == 0) V[t >> 5] = val;
    __syncthreads();
    if (t == 0) {
        float s = 0.f;
        #pragma unroll
        for (int w = 0; w < THREADS / 32; w++) s += V[w];
        g_scratch[(self ? NPARTS : 0) * BATCH + ((first + pl) * BATCH + b)] = s / (float)n;
    }
}

// Quad kernel: 4n dense rows, all four sweeps in one CTA. smem=(4n+16)*ld.
template<int NC4, int THREADS, int MINCTAS>
__global__ void __launch_bounds__(THREADS, MINCTAS)
quad_kernel(const float* __restrict__ pred, const float* __restrict__ pc, int first)
{
    const int pl = blockIdx.x >> 11;
    const int b  = blockIdx.x & 2047;
    const int4 d = c_desc[first + pl];
    const int n = d.x, ld = d.y, soff = d.z;

    extern __shared__ float sm[];
    const int msz = n * ld;
    float* V  = sm + 4 * msz;          // scaled: (buf*4 + g)*ld ; geometry at +8*ld
    float* xx = V + 8*ld;  float* xy = V + 9*ld;  float* xz = V + 10*ld; float* x2 = V + 11*ld;
    float* yx = V + 12*ld; float* yy = V + 13*ld; float* yz = V + 14*ld; float* y2 = V + 15*ld;

    const int t = threadIdx.x;
    const int g = t / n;               // one runtime divide
    const int r = t - g * n;
    const bool act = (g < 4);

    if (act && g == 0) {
        const float* X = pred + ((size_t)b * TOTAL_V + soff + r) * 3;
        float ax = X[0], ay = X[1], az = X[2];
        xx[r] = ax; xy[r] = ay; xz[r] = az;
        x2[r] = ax*ax + ay*ay + az*az;
    }
    if (act && g == 1) {
        const float* Y = pc + ((size_t)b * TOTAL_V + soff + r) * 3;
        float bx = Y[0], by = Y[1], bz = Y[2];
        yx[r] = bx; yy[r] = by; yz[r] = bz;
        y2[r] = bx*bx + by*by + bz*bz;
    }
    for (int j = n + t; j < ld; j += THREADS) {
        #pragma unroll
        for (int a = 0; a < 8; a++) V[a*ld + j] = -1e30f;
    }
    __syncthreads();

    if (act) {
        // g0: Cxy(X,Y) g1: Cyx(Y,X) g2: Cxx g3: Cyy
        const bool lX = (g == 0) || (g == 2);
        const bool rX = (g == 1) || (g == 2);
        const float lx = lX ? xx[r] : yx[r];
        const float ly = lX ? xy[r] : yy[r];
        const float lz = lX ? xz[r] : yz[r];
        const float hl2 = 0.5f * (lX ? x2[r] : y2[r]);
        build_row<NC4>(sm + g*msz + r*ld, lx, ly, lz, hl2,
                       rX ? xx : yx, rX ? xy : yy, rX ? xz : yz, rX ? x2 : y2, n);
    }

    const float l2n = lg2f_((float)n);
    const int rg = (g < 2) ? (1 - g) : g;
    const float4* rr = (const float4*)(sm + g*msz + (size_t)r*ld);

    const float myv = eps_mainloop<NC4, 4>(V, ld, g, rg, r, act, rr, l2n);
    __syncthreads();

    float val = act ? ((g < 2) ? myv : -myv) : 0.f;
    #pragma unroll
    for (int o = 16; o; o >>= 1) val += __shfl_xor_sync(0xffffffffu, val, o);
    if ((t & 31) == 0) V[t >> 5] = val;
    __syncthreads();
    if (t == 0) {
        float s = 0.f;
        #pragma unroll
        for (int w = 0; w < THREADS / 32; w++) s += V[w];
        g_scratch[(first + pl) * BATCH + b] = s / (float)n;
    }
}

// Two-stage deterministic reduction.
__global__ void reduce_partial_kernel()
{
    __shared__ float red[32];
    const int chunk = (2 * NPARTS * BATCH) / NRED;   // 2048
    const int base = blockIdx.x * chunk;
    float s = 0.f;
    for (int i = threadIdx.x; i < chunk; i += 1024) s += g_scratch[base + i];
    #pragma unroll
    for (int o = 16; o; o >>= 1) s += __shfl_xor_sync(0xffffffffu, s, o);
    if ((threadIdx.x & 31) == 0) red[threadIdx.x >> 5] = s;
    __syncthreads();
    if (threadIdx.x < 32) {
        float v = red[threadIdx.x];
        #pragma unroll
        for (int o = 16; o; o >>= 1) v += __shfl_xor_sync(0xffffffffu, v, o);
        if (threadIdx.x == 0) g_partial[blockIdx.x] = v;
    }
}

__global__ void reduce_final_kernel(float* __restrict__ out)
{
    if (threadIdx.x == 0) {
        float acc = 0.f;
        for (int i = 0; i < NRED; i++) acc += g_partial[i];
        out[0] = acc * (1.0f / (float)BATCH);
    }
}

extern "C" void kernel_launch(void* const* d_in, const int* in_sizes, int n_in,
                              void* d_out, int out_size)
{
    const float* pred = (const float*)d_in[0];
    const float* pc   = (const float*)d_in[1];

    const int smQ10 = (4*40 + 16) * 44 * 4;   // 30,976 x6 = 186KB
    const int smQ9  = (4*35 + 16) * 36 * 4;   // 22,464
    const int smQ13 = (4*50 + 16) * 52 * 4;   // 44,928
    const int smP11 = (2*44 + 12) * 44 * 4;   // 17,600
    const int smP12 = (2*45 + 12) * 52 * 4;   // 21,216
    const int smP7  = (2*28 + 12) * 28 * 4;   //  7,616
    const int smP16 = (2*64 + 12) * 68 * 4;   // 38,080 x5 = 190KB
    const int smP15 = (2*60 + 12) * 60 * 4;   // 31,680 x7 = 222KB
    const int smP23 = (2*92 + 12) * 92 * 4;   // 72,128 x3 = 216KB

    cudaFuncSetAttribute((const void*)quad_kernel<10,160,6>, cudaFuncAttributeMaxDynamicSharedMemorySize, smQ10);
    cudaFuncSetAttribute((const void*)quad_kernel< 9,160,6>, cudaFuncAttributeMaxDynamicSharedMemorySize, smQ9);
    cudaFuncSetAttribute((const void*)quad_kernel<13,224,4>, cudaFuncAttributeMaxDynamicSharedMemorySize, smQ13);
    cudaFuncSetAttribute((const void*)pair_kernel<11, 96,10>, cudaFuncAttributeMaxDynamicSharedMemorySize, smP11);
    cudaFuncSetAttribute((const void*)pair_kernel<12, 96,10>, cudaFuncAttributeMaxDynamicSharedMemorySize, smP12);
    cudaFuncSetAttribute((const void*)pair_kernel< 7, 64,15>, cudaFuncAttributeMaxDynamicSharedMemorySize, smP7);
    cudaFuncSetAttribute((const void*)pair_kernel<16,128, 5>, cudaFuncAttributeMaxDynamicSharedMemorySize, smP16);
    cudaFuncSetAttribute((const void*)pair_kernel<15,128, 7>, cudaFuncAttributeMaxDynamicSharedMemorySize, smP15);
    cudaFuncSetAttribute((const void*)pair_kernel<23,192, 3>, cudaFuncAttributeMaxDynamicSharedMemorySize, smP23);

    // Multi-stream fork/join (capture-safe); created once on the uncaptured correctness call.
    static cudaStream_t sx[3];
    static cudaEvent_t evr, evd[3];
    static int sok = -1;
    if (sok < 0) {
        sok = 1;
        for (int i = 0; i < 3; i++)
            if (cudaStreamCreateWithFlags(&sx[i], cudaStreamNonBlocking) != cudaSuccess) sok = 0;
        if (cudaEventCreateWithFlags(&evr, cudaEventDisableTiming) != cudaSuccess) sok = 0;
        for (int i = 0; i < 3; i++)
            if (cudaEventCreateWithFlags(&evd[i], cudaEventDisableTiming) != cudaSuccess) sok = 0;
    }
    cudaStream_t s1 = 0, s2 = 0, s3 = 0;
    if (sok) {
        cudaEventRecord(evr, 0);
        for (int i = 0; i < 3; i++) cudaStreamWaitEvent(sx[i], evr, 0);
        s1 = sx[0]; s2 = sx[1]; s3 = sx[2];
    }

    // Balanced packing (work units = 4*n*NC4 per part):
    pair_kernel<23,192, 3><<<1 * 2 * BATCH, 192, smP23, 0>>>(pred, pc, 19);  // n=92
    pair_kernel<12, 96,10><<<2 * 2 * BATCH,  96, smP12, 0>>>(pred, pc, 10);  // n=45,45
    pair_kernel< 7, 64,15><<<1 * 2 * BATCH,  64, smP7 , 0>>>(pred, pc, 12);  // n=28

    pair_kernel<11, 96,10><<<6 * 2 * BATCH,  96, smP11, s1>>>(pred, pc,  4); // n=41..44
    quad_kernel< 9,160,6> <<<2 * BATCH,     160, smQ9 , s1>>>(pred, pc,  1); // n=34,35

    pair_kernel<16,128, 5><<<2 * 2 * BATCH, 128, smP16, s2>>>(pred, pc, 13); // n=61,62
    pair_kernel<15,128, 7><<<1 * 2 * BATCH, 128, smP15, s2>>>(pred, pc, 17); // n=58
    quad_kernel<13,224,4> <<<1 * BATCH,     224, smQ13, s2>>>(pred, pc,  3); // n=50

    pair_kernel<16,128, 5><<<2 * 2 * BATCH, 128, smP16, s3>>>(pred, pc, 15); // n=62,64
    pair_kernel<15,128, 7><<<1 * 2 * BATCH, 128, smP15, s3>>>(pred, pc, 18); // n=60
    quad_kernel<10,160,6> <<<1 * BATCH,     160, smQ10, s3>>>(pred, pc,  0); // n=40

    if (sok) {
        for (int i = 0; i < 3; i++) {
            cudaEventRecord(evd[i], sx[i]);
            cudaStreamWaitEvent(0, evd[i], 0);
        }
    }
    reduce_partial_kernel<<<NRED, 1024, 0, 0>>>();
    reduce_final_kernel<<<1, 64, 0, 0>>>((float*)d_out);
}